// round 5
// baseline (speedup 1.0000x reference)
#include <cuda_runtime.h>
#include <math.h>

#define N_NODES 100000
#define MDIM 256
#define BSZ 20000
#define DIVIDE 8

#define BR 64
#define BM 64
#define KC 16
#define APITCH 17
#define WPITCH 68

typedef unsigned long long u64;

__device__ int g_ids64;
__device__ float g_mg[BSZ * MDIM];   // gathered mem[ids] for current step
__device__ float g_dg[BSZ * MDIM];   // gathered dtdg_output[ids] (last step only)

// ---------------------------------------------------------------------------
// Packed f32x2 helpers (sm_100+ PTX; ptxas never emits FFMA2 from C++).
// Lane order: low 32 bits = element 0, high 32 bits = element 1.
// ---------------------------------------------------------------------------
__device__ __forceinline__ u64 pack2(float x) {
    u64 r;
    asm("mov.b64 %0, {%1, %1};" : "=l"(r) : "f"(x));
    return r;
}
__device__ __forceinline__ void fma2(u64& d, u64 a, u64 b) {
    asm("fma.rn.f32x2 %0, %1, %2, %0;" : "+l"(d) : "l"(a), "l"(b));
}
__device__ __forceinline__ void unpack2(float& lo, float& hi, u64 v) {
    asm("mov.b64 {%0, %1}, %2;" : "=f"(lo), "=f"(hi) : "l"(v));
}

// ---------------------------------------------------------------------------
// node_ids dtype detection: ids are a permutation slice (unique within batch,
// values in [0, 100000)). If stored as little-endian int64, the high 32-bit
// words are all zero; if int32, the odd words are distinct ids and cannot all
// be zero. Check 16 of them.
// ---------------------------------------------------------------------------
__global__ void detect_ids_kernel(const int* ids32) {
    bool is64 = true;
    for (int i = 0; i < 16; i++)
        if (ids32[2 * i + 1] != 0) is64 = false;
    g_ids64 = is64 ? 1 : 0;
}

__device__ __forceinline__ int load_id(const void* ids, int idx) {
    if (g_ids64) return (int)((const long long*)ids)[idx];
    return ((const int*)ids)[idx];
}

// ---------------------------------------------------------------------------
// Copy initial memory into d_out (working state).
// ---------------------------------------------------------------------------
__global__ void copy_mem_kernel(float4* __restrict__ dst,
                                const float4* __restrict__ src, int n4) {
    int i = blockIdx.x * blockDim.x + threadIdx.x;
    if (i < n4) dst[i] = src[i];
}

// ---------------------------------------------------------------------------
// Per-step gather: g_mg[b] = mem[ids[step][b]]; last step also gathers dtdg.
// One block per row, 64 threads, float4 (one 16B load per thread).
// ---------------------------------------------------------------------------
__global__ void gather_kernel(const float* __restrict__ mem,
                              const float* __restrict__ dtdg,
                              const void* __restrict__ ids,
                              int step, int do_dg) {
    int b = blockIdx.x;
    int id = load_id(ids, step * BSZ + b);
    int t = threadIdx.x;  // 0..63
    const float4* src = (const float4*)(mem + (size_t)id * MDIM);
    ((float4*)(g_mg + (size_t)b * MDIM))[t] = src[t];
    if (do_dg) {
        const float4* s2 = (const float4*)(dtdg + (size_t)id * MDIM);
        ((float4*)(g_dg + (size_t)b * MDIM))[t] = s2[t];
    }
}

// ---------------------------------------------------------------------------
// One K=256 pass over source A (row-linear [BSZ][256]) accumulating NPAIR
// accumulator pairs, using packed f32x2 FMA (2 columns per instruction).
// acc[p][i][jp] holds columns (c0+2*jp, c0+2*jp+1) for row r0+i.
// 256 threads, 64x64 tile, 4x4 register tile per thread.
// ---------------------------------------------------------------------------
template <int NPAIR>
__device__ __forceinline__ void phase_pass(
    const float* __restrict__ A,
    const float* __restrict__ Wa, const float* __restrict__ Wb,
    const float* __restrict__ Wc, const float* __restrict__ Wd,
    float* __restrict__ As,
    float* __restrict__ Wsa, float* __restrict__ Wsb,
    float* __restrict__ Wsc, float* __restrict__ Wsd,
    u64 (*acc)[4][2],
    int tid, int rb) {
    const int ty = tid >> 4, tx = tid & 15;
    const int r0 = ty * 4, c0 = tx * 4;

    for (int k0 = 0; k0 < MDIM; k0 += KC) {
        // Load A tile [64 rows x 16 k]
#pragma unroll
        for (int i = 0; i < 4; i++) {
            int idx = tid + 256 * i;
            int r = idx >> 4, k = idx & 15;
            int row = rb + r;
            if (row >= BSZ) row = BSZ - 1;
            As[r * APITCH + k] = A[(size_t)row * MDIM + k0 + k];
        }
        // Load W tiles [16 k x 64 c] (k-major in shared; rows are 16B-aligned:
        // WPITCH*4 = 272 = 17*16)
#pragma unroll
        for (int i = 0; i < 4; i++) {
            int idx = tid + 256 * i;
            int c = idx >> 4, k = idx & 15;
            int off = c * MDIM + k0 + k;
            Wsa[k * WPITCH + c] = Wa[off];
            Wsb[k * WPITCH + c] = Wb[off];
            if (NPAIR == 2) {
                Wsc[k * WPITCH + c] = Wc[off];
                Wsd[k * WPITCH + c] = Wd[off];
            }
        }
        __syncthreads();
#pragma unroll
        for (int k = 0; k < KC; k++) {
            u64 ap[4];
#pragma unroll
            for (int i = 0; i < 4; i++) ap[i] = pack2(As[(r0 + i) * APITCH + k]);
            ulonglong2 wa = *(const ulonglong2*)&Wsa[k * WPITCH + c0];
            ulonglong2 wb = *(const ulonglong2*)&Wsb[k * WPITCH + c0];
#pragma unroll
            for (int i = 0; i < 4; i++) {
                fma2(acc[0][i][0], ap[i], wa.x);
                fma2(acc[0][i][1], ap[i], wa.y);
                fma2(acc[1][i][0], ap[i], wb.x);
                fma2(acc[1][i][1], ap[i], wb.y);
            }
            if (NPAIR == 2) {
                ulonglong2 wc = *(const ulonglong2*)&Wsc[k * WPITCH + c0];
                ulonglong2 wd = *(const ulonglong2*)&Wsd[k * WPITCH + c0];
#pragma unroll
                for (int i = 0; i < 4; i++) {
                    fma2(acc[2][i][0], ap[i], wc.x);
                    fma2(acc[2][i][1], ap[i], wc.y);
                    fma2(acc[3][i][0], ap[i], wd.x);
                    fma2(acc[3][i][1], ap[i], wd.y);
                }
            }
        }
        __syncthreads();
    }
}

// ---------------------------------------------------------------------------
// Fused step kernel: GEMM (only the weight rows actually consumed) + gate
// nonlinearities + scatter into mem. Grid: (ceil(B/64), 256/64).
// Non-last steps only need W_h rows [256:512) and [768:1024).
// ---------------------------------------------------------------------------
template <int IS_LAST>
__global__ void __launch_bounds__(256) step_kernel(
    float* __restrict__ mem,
    const float* __restrict__ messages,
    const void* __restrict__ ids,
    const float* __restrict__ WCw, const float* __restrict__ WCb,
    const float* __restrict__ WDw, const float* __restrict__ WDb,
    const float* __restrict__ Whw, const float* __restrict__ Whb,
    int step) {
    constexpr int NACC = IS_LAST ? 4 : 2;
    __shared__ __align__(16) float As[BR * APITCH];
    __shared__ __align__(16) float Ws[NACC][KC * WPITCH];
    __shared__ int s_ids[BR];

    const int tid = threadIdx.x;
    const int rb = blockIdx.x * BR;
    const int cb = blockIdx.y * BM;

    if (tid < BR) {
        int row = rb + tid;
        s_ids[tid] = load_id(ids, step * BSZ + (row < BSZ ? row : BSZ - 1));
    }

    u64 acc[NACC][4][2];
    const u64 zero = pack2(0.0f);
#pragma unroll
    for (int p = 0; p < NACC; p++)
#pragma unroll
        for (int i = 0; i < 4; i++)
#pragma unroll
            for (int jp = 0; jp < 2; jp++) acc[p][i][jp] = zero;

    const float* msg = messages + (size_t)step * BSZ * MDIM;

    // Phase 0: A = messages.  gateC += msg . W_C[cb+c], hC += msg . W_C[256+cb+c]
    phase_pass<1>(msg, WCw + (size_t)cb * MDIM, WCw + (size_t)(256 + cb) * MDIM,
                  nullptr, nullptr, As, Ws[0], Ws[1], nullptr, nullptr,
                  acc, tid, rb);

    if (IS_LAST) {
        // Phase 1: A = m_g. gateC += mg.W_h[256+m], hC += mg.W_h[768+m],
        //                   gateD += mg.W_h[m],      hD += mg.W_h[512+m]
        phase_pass<2>(g_mg,
                      Whw + (size_t)(256 + cb) * MDIM,
                      Whw + (size_t)(768 + cb) * MDIM,
                      Whw + (size_t)cb * MDIM,
                      Whw + (size_t)(512 + cb) * MDIM,
                      As, Ws[0], Ws[1], Ws[2], Ws[3], acc, tid, rb);
        // Phase 2: A = dtdg[ids]. gateD += d.W_D[m], hD += d.W_D[256+m]
        phase_pass<1>(g_dg, WDw + (size_t)cb * MDIM,
                      WDw + (size_t)(256 + cb) * MDIM,
                      nullptr, nullptr, As, Ws[0], Ws[1], nullptr, nullptr,
                      acc + 2, tid, rb);
    } else {
        // Phase 1: A = m_g. gateC += mg.W_h[256+m], hC += mg.W_h[768+m]
        phase_pass<1>(g_mg,
                      Whw + (size_t)(256 + cb) * MDIM,
                      Whw + (size_t)(768 + cb) * MDIM,
                      nullptr, nullptr, As, Ws[0], Ws[1], nullptr, nullptr,
                      acc, tid, rb);
    }

    // Unpack packed accumulators to scalar floats.
    float accf[NACC][4][4];
#pragma unroll
    for (int p = 0; p < NACC; p++)
#pragma unroll
        for (int i = 0; i < 4; i++)
#pragma unroll
            for (int jp = 0; jp < 2; jp++)
                unpack2(accf[p][i][2 * jp], accf[p][i][2 * jp + 1], acc[p][i][jp]);

    // Epilogue: biases + nonlinearities + blend + scatter.
    const int ty = tid >> 4, tx = tid & 15;
    const int r0 = ty * 4, c0 = tx * 4;
#pragma unroll
    for (int i = 0; i < 4; i++) {
        int row = rb + r0 + i;
        if (row < BSZ) {
            int id = s_ids[r0 + i];
#pragma unroll
            for (int j = 0; j < 4; j++) {
                int m = cb + c0 + j;
                float mg = g_mg[(size_t)row * MDIM + m];
                float gpre = accf[0][i][j] + WCb[m] + Whb[256 + m];
                float hpre = accf[1][i][j] + WCb[256 + m] + Whb[768 + m];
                float gc = 1.0f / (1.0f + expf(-gpre));
                float hc = tanhf(hpre);
                float out;
                if (IS_LAST) {
                    float gdpre = accf[2][i][j] + WDb[m] + Whb[m];
                    float hdpre = accf[3][i][j] + WDb[256 + m] + Whb[512 + m];
                    float gd = 1.0f / (1.0f + expf(-gdpre));
                    float hd = tanhf(hdpre);
                    out = 0.5f * (gd * hd + gc * hc + (2.0f - gd - gc) * mg);
                } else {
                    out = gc * mg + (1.0f - gc) * hc;
                }
                mem[(size_t)id * MDIM + m] = out;
            }
        }
    }
}

// ---------------------------------------------------------------------------
extern "C" void kernel_launch(void* const* d_in, const int* in_sizes, int n_in,
                              void* d_out, int out_size) {
    const float* memory   = (const float*)d_in[0];
    const void*  ids      = d_in[1];
    const float* messages = (const float*)d_in[2];
    const float* dtdg     = (const float*)d_in[3];
    const float* WCw      = (const float*)d_in[4];
    const float* WCb      = (const float*)d_in[5];
    const float* WDw      = (const float*)d_in[6];
    const float* WDb      = (const float*)d_in[7];
    const float* Whw      = (const float*)d_in[8];
    const float* Whb      = (const float*)d_in[9];
    float* mem = (float*)d_out;

    detect_ids_kernel<<<1, 1>>>((const int*)ids);

    int n4 = N_NODES * MDIM / 4;
    copy_mem_kernel<<<(n4 + 255) / 256, 256>>>((float4*)mem,
                                               (const float4*)memory, n4);

    dim3 grid((BSZ + BR - 1) / BR, MDIM / BM);
    for (int step = 0; step < DIVIDE; step++) {
        int last = (step == DIVIDE - 1);
        gather_kernel<<<BSZ, 64>>>(mem, dtdg, ids, step, last);
        if (last)
            step_kernel<1><<<grid, 256>>>(mem, messages, ids, WCw, WCb,
                                          WDw, WDb, Whw, Whb, step);
        else
            step_kernel<0><<<grid, 256>>>(mem, messages, ids, WCw, WCb,
                                          WDw, WDb, Whw, Whb, step);
    }
}

// round 6
// speedup vs baseline: 1.1371x; 1.1371x over previous
#include <cuda_runtime.h>
#include <math.h>

#define N_NODES 100000
#define MDIM 256
#define BSZ 20000
#define DIVIDE 8

#define BR 64
#define BM 64
#define KC 16
#define APITCH 20
#define WPITCH 68

typedef unsigned long long u64;

__device__ int g_ids64;
__device__ float g_mg[BSZ * MDIM];   // gathered mem[ids] for current step
__device__ float g_dg[BSZ * MDIM];   // gathered dtdg_output[ids] (last step only)

// ---------------------------------------------------------------------------
// Packed f32x2 helpers (sm_100+ PTX; ptxas never emits FFMA2 from C++).
// ---------------------------------------------------------------------------
__device__ __forceinline__ u64 pack2(float x) {
    u64 r;
    asm("mov.b64 %0, {%1, %1};" : "=l"(r) : "f"(x));
    return r;
}
__device__ __forceinline__ void fma2(u64& d, u64 a, u64 b) {
    asm("fma.rn.f32x2 %0, %1, %2, %0;" : "+l"(d) : "l"(a), "l"(b));
}
__device__ __forceinline__ void unpack2(float& lo, float& hi, u64 v) {
    asm("mov.b64 {%0, %1}, %2;" : "=f"(lo), "=f"(hi) : "l"(v));
}

// ---------------------------------------------------------------------------
// node_ids dtype detection (int64 vs int32; ids unique in [0,100000)).
// ---------------------------------------------------------------------------
__global__ void detect_ids_kernel(const int* ids32) {
    bool is64 = true;
    for (int i = 0; i < 16; i++)
        if (ids32[2 * i + 1] != 0) is64 = false;
    g_ids64 = is64 ? 1 : 0;
}

__device__ __forceinline__ int load_id(const void* ids, int idx) {
    if (g_ids64) return (int)((const long long*)ids)[idx];
    return ((const int*)ids)[idx];
}

__global__ void copy_mem_kernel(float4* __restrict__ dst,
                                const float4* __restrict__ src, int n4) {
    int i = blockIdx.x * blockDim.x + threadIdx.x;
    if (i < n4) dst[i] = src[i];
}

// ---------------------------------------------------------------------------
// Per-step gather: g_mg[b] = mem[ids[step][b]]; last step also gathers dtdg.
// ---------------------------------------------------------------------------
__global__ void gather_kernel(const float* __restrict__ mem,
                              const float* __restrict__ dtdg,
                              const void* __restrict__ ids,
                              int step, int do_dg) {
    int b = blockIdx.x;
    int id = load_id(ids, step * BSZ + b);
    int t = threadIdx.x;  // 0..63
    const float4* src = (const float4*)(mem + (size_t)id * MDIM);
    ((float4*)(g_mg + (size_t)b * MDIM))[t] = src[t];
    if (do_dg) {
        const float4* s2 = (const float4*)(dtdg + (size_t)id * MDIM);
        ((float4*)(g_dg + (size_t)b * MDIM))[t] = s2[t];
    }
}

// ---------------------------------------------------------------------------
// One K=256 pass over A ([BSZ][256] row-linear) accumulating NPAIR pairs of
// 64-col outputs with packed f32x2 FMA. Software-pipelined: chunk n+1 is
// prefetched into registers (one float4 LDG per thread per tile) while
// chunk n computes. A is consumed from shared via LDS.128 (4 k at a time).
// ---------------------------------------------------------------------------
template <int NPAIR>
__device__ __forceinline__ void phase_pass(
    const float* __restrict__ A,
    const float* __restrict__ Wa, const float* __restrict__ Wb,
    const float* __restrict__ Wc, const float* __restrict__ Wd,
    float* __restrict__ As,
    float* __restrict__ Wsa, float* __restrict__ Wsb,
    float* __restrict__ Wsc, float* __restrict__ Wsd,
    u64 (*acc)[4][2],
    int tid, int rb) {
    const int ty = tid >> 4, tx = tid & 15;
    const int r0 = ty * 4, c0 = tx * 4;

    // Staging maps: A — thread -> (row 0..63, kgroup 0..3);
    //               W — thread -> (col 0..63, kgroup 0..3).
    const int ar = tid >> 2, akg = tid & 3;
    int arow = rb + ar; if (arow >= BSZ) arow = BSZ - 1;
    const float* a_src = A + (size_t)arow * MDIM + akg * 4;
    const int wc_ = tid >> 2, wkg = tid & 3;
    const int woff = wc_ * MDIM + wkg * 4;

    float4 a_st, wa_st, wb_st, wc_st, wd_st;
    a_st  = *(const float4*)(a_src);
    wa_st = *(const float4*)(Wa + woff);
    wb_st = *(const float4*)(Wb + woff);
    if (NPAIR == 2) {
        wc_st = *(const float4*)(Wc + woff);
        wd_st = *(const float4*)(Wd + woff);
    }

    for (int k0 = 0; k0 < MDIM; k0 += KC) {
        // Commit staged chunk to shared.
        *(float4*)&As[ar * APITCH + akg * 4] = a_st;
        {
            const int kb = wkg * 4;
            Wsa[(kb + 0) * WPITCH + wc_] = wa_st.x;
            Wsa[(kb + 1) * WPITCH + wc_] = wa_st.y;
            Wsa[(kb + 2) * WPITCH + wc_] = wa_st.z;
            Wsa[(kb + 3) * WPITCH + wc_] = wa_st.w;
            Wsb[(kb + 0) * WPITCH + wc_] = wb_st.x;
            Wsb[(kb + 1) * WPITCH + wc_] = wb_st.y;
            Wsb[(kb + 2) * WPITCH + wc_] = wb_st.z;
            Wsb[(kb + 3) * WPITCH + wc_] = wb_st.w;
            if (NPAIR == 2) {
                Wsc[(kb + 0) * WPITCH + wc_] = wc_st.x;
                Wsc[(kb + 1) * WPITCH + wc_] = wc_st.y;
                Wsc[(kb + 2) * WPITCH + wc_] = wc_st.z;
                Wsc[(kb + 3) * WPITCH + wc_] = wc_st.w;
                Wsd[(kb + 0) * WPITCH + wc_] = wd_st.x;
                Wsd[(kb + 1) * WPITCH + wc_] = wd_st.y;
                Wsd[(kb + 2) * WPITCH + wc_] = wd_st.z;
                Wsd[(kb + 3) * WPITCH + wc_] = wd_st.w;
            }
        }
        __syncthreads();

        // Prefetch next chunk while computing this one.
        if (k0 + KC < MDIM) {
            const int kn = k0 + KC;
            a_st  = *(const float4*)(a_src + kn);
            wa_st = *(const float4*)(Wa + woff + kn);
            wb_st = *(const float4*)(Wb + woff + kn);
            if (NPAIR == 2) {
                wc_st = *(const float4*)(Wc + woff + kn);
                wd_st = *(const float4*)(Wd + woff + kn);
            }
        }

#pragma unroll
        for (int kg = 0; kg < KC / 4; kg++) {
            float4 av[4];
#pragma unroll
            for (int i = 0; i < 4; i++)
                av[i] = *(const float4*)&As[(r0 + i) * APITCH + kg * 4];
#pragma unroll
            for (int kk = 0; kk < 4; kk++) {
                const int k = kg * 4 + kk;
                u64 ap[4];
#pragma unroll
                for (int i = 0; i < 4; i++)
                    ap[i] = pack2(((const float*)&av[i])[kk]);
                ulonglong2 wa = *(const ulonglong2*)&Wsa[k * WPITCH + c0];
                ulonglong2 wb = *(const ulonglong2*)&Wsb[k * WPITCH + c0];
#pragma unroll
                for (int i = 0; i < 4; i++) {
                    fma2(acc[0][i][0], ap[i], wa.x);
                    fma2(acc[0][i][1], ap[i], wa.y);
                    fma2(acc[1][i][0], ap[i], wb.x);
                    fma2(acc[1][i][1], ap[i], wb.y);
                }
                if (NPAIR == 2) {
                    ulonglong2 wc = *(const ulonglong2*)&Wsc[k * WPITCH + c0];
                    ulonglong2 wd = *(const ulonglong2*)&Wsd[k * WPITCH + c0];
#pragma unroll
                    for (int i = 0; i < 4; i++) {
                        fma2(acc[2][i][0], ap[i], wc.x);
                        fma2(acc[2][i][1], ap[i], wc.y);
                        fma2(acc[3][i][0], ap[i], wd.x);
                        fma2(acc[3][i][1], ap[i], wd.y);
                    }
                }
            }
        }
        __syncthreads();
    }
}

// ---------------------------------------------------------------------------
// Fused step kernel: GEMM (only consumed weight rows) + gates + scatter.
// Grid: (ceil(B/64), 256/64). MIN_CTAS caps regs (occupancy lever).
// ---------------------------------------------------------------------------
template <int IS_LAST, int MIN_CTAS>
__global__ void __launch_bounds__(256, MIN_CTAS) step_kernel(
    float* __restrict__ mem,
    const float* __restrict__ messages,
    const void* __restrict__ ids,
    const float* __restrict__ WCw, const float* __restrict__ WCb,
    const float* __restrict__ WDw, const float* __restrict__ WDb,
    const float* __restrict__ Whw, const float* __restrict__ Whb,
    int step) {
    constexpr int NACC = IS_LAST ? 4 : 2;
    __shared__ __align__(16) float As[BR * APITCH];
    __shared__ __align__(16) float Ws[NACC][KC * WPITCH];
    __shared__ int s_ids[BR];

    const int tid = threadIdx.x;
    const int rb = blockIdx.x * BR;
    const int cb = blockIdx.y * BM;

    if (tid < BR) {
        int row = rb + tid;
        s_ids[tid] = load_id(ids, step * BSZ + (row < BSZ ? row : BSZ - 1));
    }

    u64 acc[NACC][4][2];
    const u64 zero = pack2(0.0f);
#pragma unroll
    for (int p = 0; p < NACC; p++)
#pragma unroll
        for (int i = 0; i < 4; i++)
#pragma unroll
            for (int jp = 0; jp < 2; jp++) acc[p][i][jp] = zero;

    const float* msg = messages + (size_t)step * BSZ * MDIM;

    // Phase 0: A = messages.
    phase_pass<1>(msg, WCw + (size_t)cb * MDIM, WCw + (size_t)(256 + cb) * MDIM,
                  nullptr, nullptr, As, Ws[0], Ws[1], nullptr, nullptr,
                  acc, tid, rb);

    if (IS_LAST) {
        phase_pass<2>(g_mg,
                      Whw + (size_t)(256 + cb) * MDIM,
                      Whw + (size_t)(768 + cb) * MDIM,
                      Whw + (size_t)cb * MDIM,
                      Whw + (size_t)(512 + cb) * MDIM,
                      As, Ws[0], Ws[1], Ws[2], Ws[3], acc, tid, rb);
        phase_pass<1>(g_dg, WDw + (size_t)cb * MDIM,
                      WDw + (size_t)(256 + cb) * MDIM,
                      nullptr, nullptr, As, Ws[0], Ws[1], nullptr, nullptr,
                      acc + 2, tid, rb);
    } else {
        phase_pass<1>(g_mg,
                      Whw + (size_t)(256 + cb) * MDIM,
                      Whw + (size_t)(768 + cb) * MDIM,
                      nullptr, nullptr, As, Ws[0], Ws[1], nullptr, nullptr,
                      acc, tid, rb);
    }

    float accf[NACC][4][4];
#pragma unroll
    for (int p = 0; p < NACC; p++)
#pragma unroll
        for (int i = 0; i < 4; i++)
#pragma unroll
            for (int jp = 0; jp < 2; jp++)
                unpack2(accf[p][i][2 * jp], accf[p][i][2 * jp + 1], acc[p][i][jp]);

    const int ty = tid >> 4, tx = tid & 15;
    const int r0 = ty * 4, c0 = tx * 4;
#pragma unroll
    for (int i = 0; i < 4; i++) {
        int row = rb + r0 + i;
        if (row < BSZ) {
            int id = s_ids[r0 + i];
#pragma unroll
            for (int j = 0; j < 4; j++) {
                int m = cb + c0 + j;
                float mg = g_mg[(size_t)row * MDIM + m];
                float gpre = accf[0][i][j] + WCb[m] + Whb[256 + m];
                float hpre = accf[1][i][j] + WCb[256 + m] + Whb[768 + m];
                float gc = 1.0f / (1.0f + expf(-gpre));
                float hc = tanhf(hpre);
                float out;
                if (IS_LAST) {
                    float gdpre = accf[2][i][j] + WDb[m] + Whb[m];
                    float hdpre = accf[3][i][j] + WDb[256 + m] + Whb[512 + m];
                    float gd = 1.0f / (1.0f + expf(-gdpre));
                    float hd = tanhf(hdpre);
                    out = 0.5f * (gd * hd + gc * hc + (2.0f - gd - gc) * mg);
                } else {
                    out = gc * mg + (1.0f - gc) * hc;
                }
                mem[(size_t)id * MDIM + m] = out;
            }
        }
    }
}

// ---------------------------------------------------------------------------
extern "C" void kernel_launch(void* const* d_in, const int* in_sizes, int n_in,
                              void* d_out, int out_size) {
    const float* memory   = (const float*)d_in[0];
    const void*  ids      = d_in[1];
    const float* messages = (const float*)d_in[2];
    const float* dtdg     = (const float*)d_in[3];
    const float* WCw      = (const float*)d_in[4];
    const float* WCb      = (const float*)d_in[5];
    const float* WDw      = (const float*)d_in[6];
    const float* WDb      = (const float*)d_in[7];
    const float* Whw      = (const float*)d_in[8];
    const float* Whb      = (const float*)d_in[9];
    float* mem = (float*)d_out;

    detect_ids_kernel<<<1, 1>>>((const int*)ids);

    int n4 = N_NODES * MDIM / 4;
    copy_mem_kernel<<<(n4 + 255) / 256, 256>>>((float4*)mem,
                                               (const float4*)memory, n4);

    dim3 grid((BSZ + BR - 1) / BR, MDIM / BM);
    for (int step = 0; step < DIVIDE; step++) {
        int last = (step == DIVIDE - 1);
        gather_kernel<<<BSZ, 64>>>(mem, dtdg, ids, step, last);
        if (last)
            step_kernel<1, 2><<<grid, 256>>>(mem, messages, ids, WCw, WCb,
                                             WDw, WDb, Whw, Whb, step);
        else
            step_kernel<0, 3><<<grid, 256>>>(mem, messages, ids, WCw, WCb,
                                             WDw, WDb, Whw, Whb, step);
    }
}

// round 14
// speedup vs baseline: 1.6382x; 1.4406x over previous
#include <cuda_runtime.h>
#include <cuda_bf16.h>
#include <math.h>

#define N_NODES 100000
#define MDIM 256
#define BSZ 20000
#define DIVIDE 8

typedef unsigned long long u64;
typedef unsigned int u32;

// ======================= device scratch =======================
__device__ int g_ids64;
__device__ float g_mg[BSZ * MDIM];
__device__ float g_dg[BSZ * MDIM];
__device__ __nv_bfloat16 g_msg_hi[BSZ * MDIM];
__device__ __nv_bfloat16 g_msg_lo[BSZ * MDIM];
__device__ __nv_bfloat16 g_mg_hi[BSZ * MDIM];
__device__ __nv_bfloat16 g_mg_lo[BSZ * MDIM];
__device__ __nv_bfloat16 g_WC_hi[512 * MDIM];
__device__ __nv_bfloat16 g_WC_lo[512 * MDIM];
__device__ __nv_bfloat16 g_Wh_hi[1024 * MDIM];
__device__ __nv_bfloat16 g_Wh_lo[1024 * MDIM];

// ======================= helpers =======================
__device__ __forceinline__ u64 pack2(float x) {
    u64 r; asm("mov.b64 %0, {%1, %1};" : "=l"(r) : "f"(x)); return r;
}
__device__ __forceinline__ void fma2(u64& d, u64 a, u64 b) {
    asm("fma.rn.f32x2 %0, %1, %2, %0;" : "+l"(d) : "l"(a), "l"(b));
}
__device__ __forceinline__ void unpack2(float& lo, float& hi, u64 v) {
    asm("mov.b64 {%0, %1}, %2;" : "=f"(lo), "=f"(hi) : "l"(v));
}
__device__ __forceinline__ u32 smem_u32(const void* p) {
    u32 a;
    asm("{ .reg .u64 t; cvta.to.shared.u64 t, %1; cvt.u32.u64 %0, t; }"
        : "=r"(a) : "l"(p));
    return a;
}
__device__ __forceinline__ void ldsm4(u32& r0, u32& r1, u32& r2, u32& r3, u32 addr) {
    asm volatile("ldmatrix.sync.aligned.m8n8.x4.shared.b16 {%0,%1,%2,%3}, [%4];"
                 : "=r"(r0), "=r"(r1), "=r"(r2), "=r"(r3) : "r"(addr));
}
__device__ __forceinline__ void mma16816(float* c, const u32* a, const u32* b) {
    asm volatile(
        "mma.sync.aligned.m16n8k16.row.col.f32.bf16.bf16.f32 "
        "{%0,%1,%2,%3}, {%4,%5,%6,%7}, {%8,%9}, {%0,%1,%2,%3};"
        : "+f"(c[0]), "+f"(c[1]), "+f"(c[2]), "+f"(c[3])
        : "r"(a[0]), "r"(a[1]), "r"(a[2]), "r"(a[3]), "r"(b[0]), "r"(b[1]));
}

// ======================= misc kernels =======================
__global__ void detect_ids_kernel(const int* ids32) {
    bool is64 = true;
    for (int i = 0; i < 16; i++)
        if (ids32[2 * i + 1] != 0) is64 = false;
    g_ids64 = is64 ? 1 : 0;
}
__device__ __forceinline__ int load_id(const void* ids, int idx) {
    if (g_ids64) return (int)((const long long*)ids)[idx];
    return ((const int*)ids)[idx];
}
__global__ void copy_mem_kernel(float4* __restrict__ dst,
                                const float4* __restrict__ src, int n4) {
    int i = blockIdx.x * blockDim.x + threadIdx.x;
    if (i < n4) dst[i] = src[i];
}
__global__ void wsplit_kernel(const float* __restrict__ src,
                              __nv_bfloat16* __restrict__ hi,
                              __nv_bfloat16* __restrict__ lo, int n) {
    int i = blockIdx.x * blockDim.x + threadIdx.x;
    if (i < n) {
        float x = src[i];
        __nv_bfloat16 h = __float2bfloat16(x);
        hi[i] = h;
        lo[i] = __float2bfloat16(x - __bfloat162float(h));
    }
}
__device__ __forceinline__ void store_split4(__nv_bfloat16* hi, __nv_bfloat16* lo,
                                             size_t idx, float4 v) {
    __nv_bfloat16 h0 = __float2bfloat16(v.x), h1 = __float2bfloat16(v.y);
    __nv_bfloat16 h2 = __float2bfloat16(v.z), h3 = __float2bfloat16(v.w);
    *(__nv_bfloat162*)(hi + idx)     = __nv_bfloat162(h0, h1);
    *(__nv_bfloat162*)(hi + idx + 2) = __nv_bfloat162(h2, h3);
    __nv_bfloat16 l0 = __float2bfloat16(v.x - __bfloat162float(h0));
    __nv_bfloat16 l1 = __float2bfloat16(v.y - __bfloat162float(h1));
    __nv_bfloat16 l2 = __float2bfloat16(v.z - __bfloat162float(h2));
    __nv_bfloat16 l3 = __float2bfloat16(v.w - __bfloat162float(h3));
    *(__nv_bfloat162*)(lo + idx)     = __nv_bfloat162(l0, l1);
    *(__nv_bfloat162*)(lo + idx + 2) = __nv_bfloat162(l2, l3);
}
__global__ void gather_kernel(const float* __restrict__ mem,
                              const float* __restrict__ dtdg,
                              const float* __restrict__ messages,
                              const void* __restrict__ ids,
                              int step, int do_dg) {
    int b = blockIdx.x;
    int id = load_id(ids, step * BSZ + b);
    int t = threadIdx.x;  // 0..63
    float4 v = ((const float4*)(mem + (size_t)id * MDIM))[t];
    ((float4*)(g_mg + (size_t)b * MDIM))[t] = v;
    if (do_dg) {
        ((float4*)(g_dg + (size_t)b * MDIM))[t] =
            ((const float4*)(dtdg + (size_t)id * MDIM))[t];
    } else {
        size_t idx = (size_t)b * MDIM + 4 * t;
        store_split4(g_mg_hi, g_mg_lo, idx, v);
        float4 m = ((const float4*)(messages + (size_t)step * BSZ * MDIM +
                                    (size_t)b * MDIM))[t];
        store_split4(g_msg_hi, g_msg_lo, idx, m);
    }
}

// ======================= mma.sync step kernel (non-last steps) ===============
// CTA: 64 batch rows x 128 out-n (n 0..63 = gate cols cb64..cb64+63,
// n 64..127 = h cols, same column range). 8 warps: warp tile 32 rows x 32 n.
// K loop: 2 sources (msg, mg) x 256 k in 32k chunks, bf16 hi/lo split,
// 3 mma per product pair (hh, hl, lh). Acc staged via shared fp32 for epilogue.
#define MR 64        // rows per CTA
#define MN 128       // out-n per CTA
#define MKC 32       // k per chunk
#define APITCH_T 40  // bf16 elems (80B: 16B-aligned, ldmatrix conflict-free)
#define SACC_P 132
// dyn smem: [0)=As_hi(64x40), [5120)=As_lo, [10240)=Ws_hi(128x40), [20480)=Ws_lo
// sacc (64x132 fp32 = 33792B) aliases from 0 after a barrier.
#define OFF_AH 0
#define OFF_AL 5120
#define OFF_WH 10240
#define OFF_WL 20480
#define SMEM_MMA 33792

__global__ void __launch_bounds__(256) mma_step_kernel(
    float* __restrict__ mem, const void* __restrict__ ids,
    const float* __restrict__ WCb, const float* __restrict__ Whb, int step) {
    extern __shared__ char dyn[];
    __shared__ int s_ids[MR];

    const int tid = threadIdx.x;
    const int wid = tid >> 5, lane = tid & 31;
    const int rb = blockIdx.x * MR;
    const int cb64 = blockIdx.y * 64;   // global column base (0,64,128,192)

    const u32 sb = smem_u32(dyn);
    __nv_bfloat16* As_hi = (__nv_bfloat16*)(dyn + OFF_AH);
    __nv_bfloat16* As_lo = (__nv_bfloat16*)(dyn + OFF_AL);
    __nv_bfloat16* Ws_hi = (__nv_bfloat16*)(dyn + OFF_WH);
    __nv_bfloat16* Ws_lo = (__nv_bfloat16*)(dyn + OFF_WL);
    float* sacc = (float*)dyn;

    if (tid < MR) {
        int r = rb + tid;
        s_ids[tid] = load_id(ids, step * BSZ + (r < BSZ ? r : BSZ - 1));
    }

    float acc[2][4][4];
#pragma unroll
    for (int mt = 0; mt < 2; mt++)
#pragma unroll
        for (int nt = 0; nt < 4; nt++)
#pragma unroll
            for (int q = 0; q < 4; q++) acc[mt][nt][q] = 0.0f;

    // Staging maps
    const int arow = tid >> 2, akg = tid & 3;            // A: row, 8-k group
    int agr = rb + arow; if (agr >= BSZ) agr = BSZ - 1;
    const int wn = tid >> 1, whalf = tid & 1;            // W: n row, 16-k half

    // Warp tile bases
    const int wr0 = (wid & 1) * 32;       // row base in CTA
    const int wc0 = (wid >> 1) * 32;      // n base in CTA

    for (int ph = 0; ph < 2; ph++) {
        const __nv_bfloat16* Ahi = ph ? g_mg_hi : g_msg_hi;
        const __nv_bfloat16* Alo = ph ? g_mg_lo : g_msg_lo;
        const __nv_bfloat16* Whi = ph ? g_Wh_hi : g_WC_hi;
        const __nv_bfloat16* Wlo = ph ? g_Wh_lo : g_WC_lo;
        const int g_off = ph ? 256 + cb64 : cb64;          // gate weight rows
        const int h_off = ph ? 768 + cb64 : 256 + cb64;    // h weight rows
        const int wrow = (wn < 64) ? g_off + wn : h_off + (wn - 64);

        for (int kc = 0; kc < MDIM; kc += MKC) {
            __syncthreads();  // prior chunk fully consumed
            // Stage A (hi/lo): 64 rows x 32 k, one uint4 per thread per split
            {
                const size_t goff = (size_t)agr * MDIM + kc + akg * 8;
                const int soff = arow * APITCH_T + akg * 8;
                *(uint4*)(As_hi + soff) = *(const uint4*)(Ahi + goff);
                *(uint4*)(As_lo + soff) = *(const uint4*)(Alo + goff);
            }
            // Stage W (hi/lo): 128 n x 32 k, 32B per thread per split
            {
                const size_t goff = (size_t)wrow * MDIM + kc + whalf * 16;
                const int soff = wn * APITCH_T + whalf * 16;
                *(uint4*)(Ws_hi + soff)     = *(const uint4*)(Whi + goff);
                *(uint4*)(Ws_hi + soff + 8) = *(const uint4*)(Whi + goff + 8);
                *(uint4*)(Ws_lo + soff)     = *(const uint4*)(Wlo + goff);
                *(uint4*)(Ws_lo + soff + 8) = *(const uint4*)(Wlo + goff + 8);
            }
            __syncthreads();

#pragma unroll
            for (int k16 = 0; k16 < MKC; k16 += 16) {
                // A fragments: rows wr0+mt*16, matrices per ldmatrix.x4 spec:
                // lane 0..15 -> row R0+(lane&15), k+0; lane 16..31 -> same rows, k+8
                u32 ahi[2][4], alo[2][4];
#pragma unroll
                for (int mt = 0; mt < 2; mt++) {
                    int row = wr0 + mt * 16 + (lane & 15);
                    int kof = k16 + ((lane >> 4) << 3);
                    u32 ao = (u32)((row * APITCH_T + kof) * 2);
                    ldsm4(ahi[mt][0], ahi[mt][1], ahi[mt][2], ahi[mt][3],
                          sb + OFF_AH + ao);
                    ldsm4(alo[mt][0], alo[mt][1], alo[mt][2], alo[mt][3],
                          sb + OFF_AL + ao);
                }
                // B fragments: x4 covers n-tile pair (nt2*2, nt2*2+1):
                // lanes 0-7: n=N0+l, k+0; 8-15: n=N0+l-8, k+8;
                // 16-23: n=N0+8+(l-16), k+0; 24-31: n=N0+8+(l-24), k+8
                u32 bhi[4][2], blo[4][2];
#pragma unroll
                for (int nt2 = 0; nt2 < 2; nt2++) {
                    int n = wc0 + nt2 * 16 + ((lane >> 4) << 3) + (lane & 7);
                    int kof = k16 + (((lane >> 3) & 1) << 3);
                    u32 bo = (u32)((n * APITCH_T + kof) * 2);
                    ldsm4(bhi[nt2 * 2][0], bhi[nt2 * 2][1],
                          bhi[nt2 * 2 + 1][0], bhi[nt2 * 2 + 1][1],
                          sb + OFF_WH + bo);
                    ldsm4(blo[nt2 * 2][0], blo[nt2 * 2][1],
                          blo[nt2 * 2 + 1][0], blo[nt2 * 2 + 1][1],
                          sb + OFF_WL + bo);
                }
#pragma unroll
                for (int mt = 0; mt < 2; mt++)
#pragma unroll
                    for (int nt = 0; nt < 4; nt++) {
                        mma16816(acc[mt][nt], ahi[mt], bhi[nt]);
                        mma16816(acc[mt][nt], ahi[mt], blo[nt]);
                        mma16816(acc[mt][nt], alo[mt], bhi[nt]);
                    }
            }
        }
    }

    // Stage accumulators to shared (aliases staging; barrier first).
    __syncthreads();
#pragma unroll
    for (int mt = 0; mt < 2; mt++)
#pragma unroll
        for (int nt = 0; nt < 4; nt++) {
            int r0 = wr0 + mt * 16 + (lane >> 2);
            int c0 = wc0 + nt * 8 + (lane & 3) * 2;
            sacc[r0 * SACC_P + c0]           = acc[mt][nt][0];
            sacc[r0 * SACC_P + c0 + 1]       = acc[mt][nt][1];
            sacc[(r0 + 8) * SACC_P + c0]     = acc[mt][nt][2];
            sacc[(r0 + 8) * SACC_P + c0 + 1] = acc[mt][nt][3];
        }
    __syncthreads();

    // Epilogue: pair gate (n 0..63) with h (n 64..127), blend, scatter.
    {
        const int r = tid >> 2, cg = tid & 3;
        const int row = rb + r;
        if (row < BSZ) {
            const int id = s_ids[r];
#pragma unroll
            for (int q = 0; q < 4; q++) {
                int c = cg * 16 + q * 4;
                float4 gv = *(const float4*)&sacc[r * SACC_P + c];
                float4 hv = *(const float4*)&sacc[r * SACC_P + 64 + c];
                float4 mg = *(const float4*)(g_mg + (size_t)row * MDIM + cb64 + c);
                float out[4];
                const float* gp = (const float*)&gv;
                const float* hp = (const float*)&hv;
                const float* mp = (const float*)&mg;
#pragma unroll
                for (int j = 0; j < 4; j++) {
                    int m = cb64 + c + j;
                    float gpre = gp[j] + WCb[m] + Whb[256 + m];
                    float hpre = hp[j] + WCb[256 + m] + Whb[768 + m];
                    float gc = 1.0f / (1.0f + expf(-gpre));
                    float hc = tanhf(hpre);
                    out[j] = gc * mp[j] + (1.0f - gc) * hc;
                }
                *(float4*)(mem + (size_t)id * MDIM + cb64 + c) =
                    make_float4(out[0], out[1], out[2], out[3]);
            }
        }
    }
}

// ======================= FFMA2 last-step kernel (validated path) =============
#define BR 64
#define BM 64
#define KC 16
#define APITCH 20
#define WPITCH 68

template <int NPAIR>
__device__ __forceinline__ void phase_pass(
    const float* __restrict__ A,
    const float* __restrict__ Wa, const float* __restrict__ Wb,
    const float* __restrict__ Wc, const float* __restrict__ Wd,
    float* __restrict__ As,
    float* __restrict__ Wsa, float* __restrict__ Wsb,
    float* __restrict__ Wsc, float* __restrict__ Wsd,
    u64 (*acc)[4][2],
    int tid, int rb) {
    const int ty = tid >> 4, tx = tid & 15;
    const int r0 = ty * 4, c0 = tx * 4;

    const int ar = tid >> 2, akg = tid & 3;
    int arow = rb + ar; if (arow >= BSZ) arow = BSZ - 1;
    const float* a_src = A + (size_t)arow * MDIM + akg * 4;
    const int wc_ = tid >> 2, wkg = tid & 3;
    const int woff = wc_ * MDIM + wkg * 4;

    float4 a_st, wa_st, wb_st, wc_st, wd_st;
    a_st  = *(const float4*)(a_src);
    wa_st = *(const float4*)(Wa + woff);
    wb_st = *(const float4*)(Wb + woff);
    if (NPAIR == 2) {
        wc_st = *(const float4*)(Wc + woff);
        wd_st = *(const float4*)(Wd + woff);
    }

    for (int k0 = 0; k0 < MDIM; k0 += KC) {
        *(float4*)&As[ar * APITCH + akg * 4] = a_st;
        {
            const int kb = wkg * 4;
            Wsa[(kb + 0) * WPITCH + wc_] = wa_st.x;
            Wsa[(kb + 1) * WPITCH + wc_] = wa_st.y;
            Wsa[(kb + 2) * WPITCH + wc_] = wa_st.z;
            Wsa[(kb + 3) * WPITCH + wc_] = wa_st.w;
            Wsb[(kb + 0) * WPITCH + wc_] = wb_st.x;
            Wsb[(kb + 1) * WPITCH + wc_] = wb_st.y;
            Wsb[(kb + 2) * WPITCH + wc_] = wb_st.z;
            Wsb[(kb + 3) * WPITCH + wc_] = wb_st.w;
            if (NPAIR == 2) {
                Wsc[(kb + 0) * WPITCH + wc_] = wc_st.x;
                Wsc[(kb + 1) * WPITCH + wc_] = wc_st.y;
                Wsc[(kb + 2) * WPITCH + wc_] = wc_st.z;
                Wsc[(kb + 3) * WPITCH + wc_] = wc_st.w;
                Wsd[(kb + 0) * WPITCH + wc_] = wd_st.x;
                Wsd[(kb + 1) * WPITCH + wc_] = wd_st.y;
                Wsd[(kb + 2) * WPITCH + wc_] = wd_st.z;
                Wsd[(kb + 3) * WPITCH + wc_] = wd_st.w;
            }
        }
        __syncthreads();

        if (k0 + KC < MDIM) {
            const int kn = k0 + KC;
            a_st  = *(const float4*)(a_src + kn);
            wa_st = *(const float4*)(Wa + woff + kn);
            wb_st = *(const float4*)(Wb + woff + kn);
            if (NPAIR == 2) {
                wc_st = *(const float4*)(Wc + woff + kn);
                wd_st = *(const float4*)(Wd + woff + kn);
            }
        }

#pragma unroll
        for (int kg = 0; kg < KC / 4; kg++) {
            float4 av[4];
#pragma unroll
            for (int i = 0; i < 4; i++)
                av[i] = *(const float4*)&As[(r0 + i) * APITCH + kg * 4];
#pragma unroll
            for (int kk = 0; kk < 4; kk++) {
                const int k = kg * 4 + kk;
                u64 ap[4];
#pragma unroll
                for (int i = 0; i < 4; i++)
                    ap[i] = pack2(((const float*)&av[i])[kk]);
                ulonglong2 wa = *(const ulonglong2*)&Wsa[k * WPITCH + c0];
                ulonglong2 wb = *(const ulonglong2*)&Wsb[k * WPITCH + c0];
#pragma unroll
                for (int i = 0; i < 4; i++) {
                    fma2(acc[0][i][0], ap[i], wa.x);
                    fma2(acc[0][i][1], ap[i], wa.y);
                    fma2(acc[1][i][0], ap[i], wb.x);
                    fma2(acc[1][i][1], ap[i], wb.y);
                }
                if (NPAIR == 2) {
                    ulonglong2 wc = *(const ulonglong2*)&Wsc[k * WPITCH + c0];
                    ulonglong2 wd = *(const ulonglong2*)&Wsd[k * WPITCH + c0];
#pragma unroll
                    for (int i = 0; i < 4; i++) {
                        fma2(acc[2][i][0], ap[i], wc.x);
                        fma2(acc[2][i][1], ap[i], wc.y);
                        fma2(acc[3][i][0], ap[i], wd.x);
                        fma2(acc[3][i][1], ap[i], wd.y);
                    }
                }
            }
        }
        __syncthreads();
    }
}

__global__ void __launch_bounds__(256, 2) last_step_kernel(
    float* __restrict__ mem,
    const float* __restrict__ messages,
    const void* __restrict__ ids,
    const float* __restrict__ WCw, const float* __restrict__ WCb,
    const float* __restrict__ WDw, const float* __restrict__ WDb,
    const float* __restrict__ Whw, const float* __restrict__ Whb,
    int step) {
    constexpr int NACC = 4;
    __shared__ __align__(16) float As[BR * APITCH];
    __shared__ __align__(16) float Ws[NACC][KC * WPITCH];
    __shared__ int s_ids[BR];

    const int tid = threadIdx.x;
    const int rb = blockIdx.x * BR;
    const int cb = blockIdx.y * BM;

    if (tid < BR) {
        int row = rb + tid;
        s_ids[tid] = load_id(ids, step * BSZ + (row < BSZ ? row : BSZ - 1));
    }

    u64 acc[NACC][4][2];
    const u64 zero = pack2(0.0f);
#pragma unroll
    for (int p = 0; p < NACC; p++)
#pragma unroll
        for (int i = 0; i < 4; i++)
#pragma unroll
            for (int jp = 0; jp < 2; jp++) acc[p][i][jp] = zero;

    const float* msg = messages + (size_t)step * BSZ * MDIM;

    phase_pass<1>(msg, WCw + (size_t)cb * MDIM, WCw + (size_t)(256 + cb) * MDIM,
                  nullptr, nullptr, As, Ws[0], Ws[1], nullptr, nullptr,
                  acc, tid, rb);
    phase_pass<2>(g_mg,
                  Whw + (size_t)(256 + cb) * MDIM,
                  Whw + (size_t)(768 + cb) * MDIM,
                  Whw + (size_t)cb * MDIM,
                  Whw + (size_t)(512 + cb) * MDIM,
                  As, Ws[0], Ws[1], Ws[2], Ws[3], acc, tid, rb);
    phase_pass<1>(g_dg, WDw + (size_t)cb * MDIM,
                  WDw + (size_t)(256 + cb) * MDIM,
                  nullptr, nullptr, As, Ws[0], Ws[1], nullptr, nullptr,
                  acc + 2, tid, rb);

    float accf[NACC][4][4];
#pragma unroll
    for (int p = 0; p < NACC; p++)
#pragma unroll
        for (int i = 0; i < 4; i++)
#pragma unroll
            for (int jp = 0; jp < 2; jp++)
                unpack2(accf[p][i][2 * jp], accf[p][i][2 * jp + 1], acc[p][i][jp]);

    const int ty = tid >> 4, tx = tid & 15;
    const int r0 = ty * 4, c0 = tx * 4;
#pragma unroll
    for (int i = 0; i < 4; i++) {
        int row = rb + r0 + i;
        if (row < BSZ) {
            int id = s_ids[r0 + i];
#pragma unroll
            for (int j = 0; j < 4; j++) {
                int m = cb + c0 + j;
                float mg = g_mg[(size_t)row * MDIM + m];
                float gpre = accf[0][i][j] + WCb[m] + Whb[256 + m];
                float hpre = accf[1][i][j] + WCb[256 + m] + Whb[768 + m];
                float gc = 1.0f / (1.0f + expf(-gpre));
                float hc = tanhf(hpre);
                float gdpre = accf[2][i][j] + WDb[m] + Whb[m];
                float hdpre = accf[3][i][j] + WDb[256 + m] + Whb[512 + m];
                float gd = 1.0f / (1.0f + expf(-gdpre));
                float hd = tanhf(hdpre);
                mem[(size_t)id * MDIM + m] =
                    0.5f * (gd * hd + gc * hc + (2.0f - gd - gc) * mg);
            }
        }
    }
}

// ======================= launch =======================
extern "C" void kernel_launch(void* const* d_in, const int* in_sizes, int n_in,
                              void* d_out, int out_size) {
    const float* memory   = (const float*)d_in[0];
    const void*  ids      = d_in[1];
    const float* messages = (const float*)d_in[2];
    const float* dtdg     = (const float*)d_in[3];
    const float* WCw      = (const float*)d_in[4];
    const float* WCb      = (const float*)d_in[5];
    const float* WDw      = (const float*)d_in[6];
    const float* WDb      = (const float*)d_in[7];
    const float* Whw      = (const float*)d_in[8];
    const float* Whb      = (const float*)d_in[9];
    float* mem = (float*)d_out;

    cudaFuncSetAttribute(mma_step_kernel,
                         cudaFuncAttributeMaxDynamicSharedMemorySize, SMEM_MMA);

    detect_ids_kernel<<<1, 1>>>((const int*)ids);

    int n4 = N_NODES * MDIM / 4;
    copy_mem_kernel<<<(n4 + 255) / 256, 256>>>((float4*)mem,
                                               (const float4*)memory, n4);

    // Pre-split weights to bf16 hi/lo (once per launch; deterministic).
    {
        __nv_bfloat16 *wc_hi, *wc_lo, *wh_hi, *wh_lo;
        cudaGetSymbolAddress((void**)&wc_hi, g_WC_hi);
        cudaGetSymbolAddress((void**)&wc_lo, g_WC_lo);
        cudaGetSymbolAddress((void**)&wh_hi, g_Wh_hi);
        cudaGetSymbolAddress((void**)&wh_lo, g_Wh_lo);
        int nC = 512 * MDIM, nH = 1024 * MDIM;
        wsplit_kernel<<<(nC + 255) / 256, 256>>>(WCw, wc_hi, wc_lo, nC);
        wsplit_kernel<<<(nH + 255) / 256, 256>>>(Whw, wh_hi, wh_lo, nH);
    }

    dim3 mm_grid((BSZ + MR - 1) / MR, MDIM / 64);
    dim3 ls_grid((BSZ + BR - 1) / BR, MDIM / BM);
    for (int step = 0; step < DIVIDE; step++) {
        int last = (step == DIVIDE - 1);
        gather_kernel<<<BSZ, 64>>>(mem, dtdg, messages, ids, step, last);
        if (last)
            last_step_kernel<<<ls_grid, 256>>>(mem, messages, ids, WCw, WCb,
                                               WDw, WDb, Whw, Whb, step);
        else
            mma_step_kernel<<<mm_grid, 256, SMEM_MMA>>>(mem, ids, WCb, Whb, step);
    }
}